// round 13
// baseline (speedup 1.0000x reference)
#include <cuda_runtime.h>
#include <cuda_bf16.h>
#include <cstdint>

#define NROWS 4096
#define DDIM  512
#define NCLS  64
#define BM    128
#define BK    64
#define NCHUNK (DDIM / BK)   // 8
#define SSTR  72             // smem row stride in bf16 elems (64 data + 8 pad = 144 B)
#define NTILES 528           // 32*33/2 upper-triangle tiles

// ---------------- device scratch (static; no allocation) ----------------
__device__ __nv_bfloat16 g_Xb[NROWS * DDIM];   // 4 MB bf16 copy of X
__device__ float g_sq[NROWS];
__device__ float g_negsum[NROWS];
__device__ int   g_cls[NROWS];
__device__ float g_loss;
__device__ int   g_cnt;
__device__ int   g_done;

// ---------------- PTX helpers (all base-sm_103 legal) ----------------
__device__ __forceinline__ uint32_t smem_u32(const void* p) {
    uint32_t a;
    asm("{ .reg .u64 t; cvta.to.shared.u64 t, %1; cvt.u32.u64 %0, t; }" : "=r"(a) : "l"(p));
    return a;
}

#define CP_ASYNC16(dst_u32, src_ptr) \
    asm volatile("{ .reg .u64 g; cvta.to.global.u64 g, %1; cp.async.cg.shared.global [%0], [g], 16; }" \
                 :: "r"(dst_u32), "l"(src_ptr) : "memory")
#define CP_COMMIT() asm volatile("cp.async.commit_group;" ::: "memory")
#define CP_WAIT(n)  asm volatile("cp.async.wait_group %0;" :: "n"(n) : "memory")

#define LDSM_X4(r, addr) \
    asm volatile("ldmatrix.sync.aligned.m8n8.x4.shared.b16 {%0,%1,%2,%3}, [%4];" \
                 : "=r"((r)[0]), "=r"((r)[1]), "=r"((r)[2]), "=r"((r)[3]) : "r"(addr))

#define MMA_BF16(d, a, b0, b1) \
    asm volatile("mma.sync.aligned.m16n8k16.row.col.f32.bf16.bf16.f32 " \
                 "{%0,%1,%2,%3}, {%4,%5,%6,%7}, {%8,%9}, {%0,%1,%2,%3};" \
                 : "+f"((d)[0]), "+f"((d)[1]), "+f"((d)[2]), "+f"((d)[3]) \
                 : "r"((a)[0]), "r"((a)[1]), "r"((a)[2]), "r"((a)[3]), "r"(b0), "r"(b1))

// ---------------- Pass 1: convert + row norms + class ids + zero accumulators ----------------
__global__ __launch_bounds__(256) void pass1_kernel(const float* __restrict__ X,
                                                    const int* __restrict__ TW) {
    int tid = threadIdx.x;
    // Detect target dtype: if buffer is int64 (LE, values < 64), every odd 32-bit
    // word of the first 512 words is 0; if int32, those words are class ids.
    int pred = (TW[2 * tid + 1] != 0);
    int is32 = __syncthreads_or(pred);

    int wid = tid >> 5, lid = tid & 31;
    int row = blockIdx.x * 8 + wid;
    const float4* src = (const float4*)(X + (size_t)row * DDIM);
    float s = 0.f;
#pragma unroll
    for (int t = 0; t < 4; t++) {
        float4 v = src[lid + 32 * t];
        s = fmaf(v.x, v.x, s); s = fmaf(v.y, v.y, s);
        s = fmaf(v.z, v.z, s); s = fmaf(v.w, v.w, s);
        __nv_bfloat162 p0 = __floats2bfloat162_rn(v.x, v.y);
        __nv_bfloat162 p1 = __floats2bfloat162_rn(v.z, v.w);
        uint2 u;
        u.x = *(const uint32_t*)&p0;
        u.y = *(const uint32_t*)&p1;
        *(uint2*)(g_Xb + (size_t)row * DDIM + (lid + 32 * t) * 4) = u;
    }
#pragma unroll
    for (int o = 16; o; o >>= 1) s += __shfl_xor_sync(0xffffffffu, s, o);
    if (lid == 0) {
        g_sq[row] = s;
        g_negsum[row] = 0.f;
        g_cls[row] = is32 ? TW[row] : TW[2 * row];
    }
    if (blockIdx.x == 0 && tid == 0) { g_loss = 0.f; g_cnt = 0; }
}

// ---------------- Pass 2: HMMA GEMM, triangle-only grid + fused row+col neg_sum epilogue ----
#define SM_SQI  0
#define SM_SQJ  512
#define SM_CI   1024
#define SM_CJ   1536
#define SM_NEGR 2048
#define SM_NEGC 2560
#define SM_A0   3072
#define SM_A1   21504
#define SM_B0   39936
#define SM_B1   58368
#define SM2_TOTAL 76800

__global__ __launch_bounds__(256, 2) void pass2_kernel() {
    // linear tile id -> (I, J) with J >= I over 32x32 block grid
    int rem = blockIdx.x, I = 0, rowlen = 32;
    while (rem >= rowlen) { rem -= rowlen; rowlen--; I++; }
    int J = I + rem;

    extern __shared__ char smem[];
    uint32_t sb = smem_u32(smem);
    int tid = threadIdx.x;
    int lane = tid & 31, wid = tid >> 5;
    int warp_m = wid >> 2, warp_n = wid & 3;           // 2 x 4 warp grid
    int m0 = warp_m * 64, n0 = warp_n * 32;            // 64x32 per warp
    int rowA0 = I * BM;
    int rowB0 = J * BM;

    float* sSqi = (float*)(smem + SM_SQI);
    float* sSqj = (float*)(smem + SM_SQJ);
    int*   sCi  = (int*)(smem + SM_CI);
    int*   sCj  = (int*)(smem + SM_CJ);
    float* sNegR = (float*)(smem + SM_NEGR);
    float* sNegC = (float*)(smem + SM_NEGC);

    if (tid < 128) {
        sSqi[tid] = g_sq[rowA0 + tid];
        sCi[tid]  = g_cls[rowA0 + tid];
        sNegR[tid] = 0.f;
    } else {
        int r = tid - 128;
        sSqj[r] = g_sq[rowB0 + r];
        sCj[r]  = g_cls[rowB0 + r];
        sNegC[r] = 0.f;
    }

    float acc[4][4][4];
#pragma unroll
    for (int i = 0; i < 4; i++)
#pragma unroll
        for (int j = 0; j < 4; j++)
#pragma unroll
            for (int e = 0; e < 4; e++) acc[i][j][e] = 0.f;

    auto issue = [&](int c, int b) {
        const __nv_bfloat16* gA = g_Xb + (size_t)rowA0 * DDIM + c * BK;
        const __nv_bfloat16* gB = g_Xb + (size_t)rowB0 * DDIM + c * BK;
        uint32_t dA = sb + (b ? SM_A1 : SM_A0);
        uint32_t dB = sb + (b ? SM_B1 : SM_B0);
#pragma unroll
        for (int t = 0; t < 4; t++) {
            int idx = tid + t * 256;           // 0..1023
            int r = idx >> 3, kk = idx & 7;    // 128 rows x 8 x 16B
            uint32_t doff = r * (SSTR * 2) + kk * 16;
            CP_ASYNC16(dA + doff, (const char*)gA + (size_t)r * (DDIM * 2) + kk * 16);
            CP_ASYNC16(dB + doff, (const char*)gB + (size_t)r * (DDIM * 2) + kk * 16);
        }
    };

    issue(0, 0);
    CP_COMMIT();

    int g  = lane >> 3, l8 = lane & 7;
    int arow = (g & 1) * 8 + l8, akoff = (g >> 1) * 8;
    int brow = (g >> 1) * 8 + l8, bkoff = (g & 1) * 8;

    for (int c = 0; c < NCHUNK; c++) {
        int b = c & 1;
        if (c + 1 < NCHUNK) { issue(c + 1, b ^ 1); CP_COMMIT(); CP_WAIT(1); }
        else                { CP_WAIT(0); }
        __syncthreads();

        uint32_t sA = sb + (b ? SM_A1 : SM_A0);
        uint32_t sB = sb + (b ? SM_B1 : SM_B0);
#pragma unroll
        for (int ks = 0; ks < 4; ks++) {
            int k0 = ks * 16;
            uint32_t afr[4][4];
#pragma unroll
            for (int mf = 0; mf < 4; mf++) {
                uint32_t ad = sA + 2u * ((m0 + mf * 16 + arow) * SSTR + k0 + akoff);
                LDSM_X4(afr[mf], ad);
            }
            uint32_t bfr[2][4];
#pragma unroll
            for (int p = 0; p < 2; p++) {
                uint32_t bd = sB + 2u * ((n0 + p * 16 + brow) * SSTR + k0 + bkoff);
                LDSM_X4(bfr[p], bd);
            }
#pragma unroll
            for (int mf = 0; mf < 4; mf++)
#pragma unroll
                for (int nf = 0; nf < 4; nf++) {
                    uint32_t b0 = bfr[nf >> 1][(nf & 1) * 2];
                    uint32_t b1 = bfr[nf >> 1][(nf & 1) * 2 + 1];
                    MMA_BF16(acc[mf][nf], afr[mf], b0, b1);
                }
        }
        __syncthreads();
    }

    // --- Epilogue ---
    int qr = lane >> 2, qc = lane & 3;
    float colacc[8];
#pragma unroll
    for (int t = 0; t < 8; t++) colacc[t] = 0.f;

#pragma unroll
    for (int mf = 0; mf < 4; mf++) {
        int il0 = m0 + mf * 16 + qr;
        int il1 = il0 + 8;
        float sq0 = sSqi[il0], sq1 = sSqi[il1];
        int   cc0 = sCi[il0],  cc1 = sCi[il1];
        float s0 = 0.f, s1 = 0.f;
#pragma unroll
        for (int nf = 0; nf < 4; nf++) {
            int jl = n0 + nf * 8 + 2 * qc;
#pragma unroll
            for (int e = 0; e < 2; e++) {
                int j = jl + e;
                float sqj = sSqj[j];
                int   cj  = sCj[j];
                float d2a = fmaxf(fmaf(-2.f, acc[mf][nf][e], sq0 + sqj), 0.f);
                float da; asm("sqrt.approx.f32 %0, %1;" : "=f"(da) : "f"(d2a));
                float ea; asm("ex2.approx.f32 %0, %1;" : "=f"(ea) : "f"((1.0f - da) * 1.4426950408889634f));
                float d2b = fmaxf(fmaf(-2.f, acc[mf][nf][2 + e], sq1 + sqj), 0.f);
                float db; asm("sqrt.approx.f32 %0, %1;" : "=f"(db) : "f"(d2b));
                float eb; asm("ex2.approx.f32 %0, %1;" : "=f"(eb) : "f"((1.0f - db) * 1.4426950408889634f));
                float fa = (cc0 != cj) ? ea : 0.f;
                float fb = (cc1 != cj) ? eb : 0.f;
                s0 += fa;
                s1 += fb;
                colacc[nf * 2 + e] += fa + fb;
            }
        }
        s0 += __shfl_xor_sync(0xffffffffu, s0, 1);
        s0 += __shfl_xor_sync(0xffffffffu, s0, 2);
        s1 += __shfl_xor_sync(0xffffffffu, s1, 1);
        s1 += __shfl_xor_sync(0xffffffffu, s1, 2);
        if (qc == 0) {
            atomicAdd(&sNegR[il0], s0);
            atomicAdd(&sNegR[il1], s1);
        }
    }

    if (J > I) {
#pragma unroll
        for (int t = 0; t < 8; t++) {
            float v = colacc[t];
            v += __shfl_xor_sync(0xffffffffu, v, 4);
            v += __shfl_xor_sync(0xffffffffu, v, 8);
            v += __shfl_xor_sync(0xffffffffu, v, 16);
            if (qr == 0) {
                int j = n0 + (t >> 1) * 8 + 2 * qc + (t & 1);
                atomicAdd(&sNegC[j], v);
            }
        }
    }

    __syncthreads();
    if (tid < 128) {
        atomicAdd(&g_negsum[rowA0 + tid], sNegR[tid]);
    } else if (J > I) {
        int r = tid - 128;
        atomicAdd(&g_negsum[rowB0 + r], sNegC[r]);
    }
}

// ---------------- Pass 3: positive pairs (dual-pair ILP) + fused finalize ----------------
#define P3Y 4                      // grid = (64, P3Y), 256 threads -> 32 warp slots/class

__global__ __launch_bounds__(256) void pass3_kernel(const float* __restrict__ X, float* out) {
    __shared__ int members[256];
    __shared__ int wcnt[8];
    int tid = threadIdx.x, wid = tid >> 5, lane = tid & 31;
    int cls = blockIdx.x;

    // Deterministic ballot-based compaction (identical ordering in all CTAs).
    int base = wid * 512;
    int cnt = 0;
#pragma unroll 4
    for (int r = 0; r < 16; r++) {
        int row = base + r * 32 + lane;
        unsigned mask = __ballot_sync(0xffffffffu, g_cls[row] == cls);
        cnt += __popc(mask);
    }
    if (lane == 0) wcnt[wid] = cnt;
    __syncthreads();
    int start = 0, ntot = 0;
#pragma unroll
    for (int w = 0; w < 8; w++) {
        int c = wcnt[w];
        if (w < wid) start += c;
        ntot += c;
    }
    int run = start;
#pragma unroll 4
    for (int r = 0; r < 16; r++) {
        int row = base + r * 32 + lane;
        bool mm = (g_cls[row] == cls);
        unsigned mask = __ballot_sync(0xffffffffu, mm);
        int pos = run + __popc(mask & ((1u << lane) - 1u));
        if (mm && pos < 256) members[pos] = row;
        run += __popc(mask);
    }
    __syncthreads();
    int n = min(ntot, 256);
    if (blockIdx.y == 0 && tid == 0 && n > 1) atomicAdd(&g_cnt, n * (n - 1));

    float loss = 0.f;
    if (n >= 2) {
        // Mirrored-balanced a-assignment: slot s handles a in {64*blk + s, 64*blk + 63 - s}.
        int s = blockIdx.y * 8 + wid;    // 0..31
        const float4* X4 = (const float4*)X;

#pragma unroll 1
        for (int k = 0; k < 8; k++) {
            int blk = k >> 1;
            int a = 64 * blk + ((k & 1) ? (63 - s) : s);
            if (a > n - 2) continue;
            int ga = members[a];
            float4 va[4];
#pragma unroll
            for (int q = 0; q < 4; q++) va[q] = __ldg(&X4[(size_t)ga * 128 + lane + 32 * q]);
            float nsa = g_negsum[ga];

            int b = a + 1;
#pragma unroll 1
            for (; b + 1 < n; b += 2) {
                int gb0 = members[b], gb1 = members[b + 1];
                float acc0 = 0.f, acc1 = 0.f;
#pragma unroll
                for (int q = 0; q < 4; q++) {
                    float4 v0 = __ldg(&X4[(size_t)gb0 * 128 + lane + 32 * q]);
                    float4 v1 = __ldg(&X4[(size_t)gb1 * 128 + lane + 32 * q]);
                    float d0x = va[q].x - v0.x, d0y = va[q].y - v0.y;
                    float d0z = va[q].z - v0.z, d0w = va[q].w - v0.w;
                    float d1x = va[q].x - v1.x, d1y = va[q].y - v1.y;
                    float d1z = va[q].z - v1.z, d1w = va[q].w - v1.w;
                    acc0 = fmaf(d0x, d0x, acc0); acc1 = fmaf(d1x, d1x, acc1);
                    acc0 = fmaf(d0y, d0y, acc0); acc1 = fmaf(d1y, d1y, acc1);
                    acc0 = fmaf(d0z, d0z, acc0); acc1 = fmaf(d1z, d1z, acc1);
                    acc0 = fmaf(d0w, d0w, acc0); acc1 = fmaf(d1w, d1w, acc1);
                }
#pragma unroll
                for (int o = 16; o; o >>= 1) {
                    acc0 += __shfl_xor_sync(0xffffffffu, acc0, o);
                    acc1 += __shfl_xor_sync(0xffffffffu, acc1, o);
                }
                if (lane == 0) {
                    float ns0 = nsa + g_negsum[gb0];
                    float ns1 = nsa + g_negsum[gb1];
                    float J0 = __logf(ns0) + sqrtf(acc0);
                    float J1 = __logf(ns1) + sqrtf(acc1);
                    float h0 = fmaxf(J0, 0.f);
                    float h1 = fmaxf(J1, 0.f);
                    loss = fmaf(h0, h0, loss);
                    loss = fmaf(h1, h1, loss);
                }
            }
            if (b < n) {   // tail pair
                int gb = members[b];
                float acc = 0.f;
#pragma unroll
                for (int q = 0; q < 4; q++) {
                    float4 vb = __ldg(&X4[(size_t)gb * 128 + lane + 32 * q]);
                    float dx = va[q].x - vb.x, dy = va[q].y - vb.y;
                    float dz = va[q].z - vb.z, dw = va[q].w - vb.w;
                    acc = fmaf(dx, dx, acc); acc = fmaf(dy, dy, acc);
                    acc = fmaf(dz, dz, acc); acc = fmaf(dw, dw, acc);
                }
#pragma unroll
                for (int o = 16; o; o >>= 1) acc += __shfl_xor_sync(0xffffffffu, acc, o);
                if (lane == 0) {
                    float ns = nsa + g_negsum[gb];
                    float Jv = __logf(ns) + sqrtf(acc);
                    float h = fmaxf(Jv, 0.f);
                    loss = fmaf(h, h, loss);
                }
            }
        }
    }
    if (lane == 0 && loss != 0.f) atomicAdd(&g_loss, loss);
    __syncthreads();

    // Fused finalize: last-done CTA writes the output (replaces pass4 launch).
    if (tid == 0) {
        __threadfence();   // make this CTA's g_loss atomic globally visible before done-count
        int done = atomicAdd(&g_done, 1);
        if (done == NCLS * P3Y - 1) {
            float L = atomicAdd(&g_loss, 0.f);   // atomic read: coherent at L2
            int   C = atomicAdd(&g_cnt, 0);
            out[0] = (C > 0) ? (L / (float)C) : 0.f;
            g_done = 0;                           // reset for next graph replay
        }
    }
}

// ---------------- host ----------------
extern "C" void kernel_launch(void* const* d_in, const int* in_sizes, int n_in,
                              void* d_out, int out_size) {
    const float* X  = (const float*)d_in[0];
    const int*   TW = (const int*)d_in[1];   // targets: int32 or int64 (auto-detected)
    float* out = (float*)d_out;

    cudaFuncSetAttribute(pass2_kernel, cudaFuncAttributeMaxDynamicSharedMemorySize, SM2_TOTAL);

    pass1_kernel<<<NROWS / 8, 256>>>(X, TW);
    pass2_kernel<<<NTILES, 256, SM2_TOTAL>>>();
    pass3_kernel<<<dim3(NCLS, P3Y), 256>>>(X, out);
}

// round 14
// speedup vs baseline: 1.0185x; 1.0185x over previous
#include <cuda_runtime.h>
#include <cuda_bf16.h>
#include <cstdint>

#define NROWS 4096
#define DDIM  512
#define NCLS  64
#define BM    128
#define BK    64
#define NCHUNK (DDIM / BK)   // 8
#define SSTR  72             // smem row stride in bf16 elems (64 data + 8 pad = 144 B)
#define NTILES 528           // 32*33/2 upper-triangle tiles

// ---------------- device scratch (static; no allocation) ----------------
__device__ __nv_bfloat16 g_Xb[NROWS * DDIM];   // 4 MB bf16 copy of X
__device__ float g_sq[NROWS];
__device__ float g_negsum[NROWS];
__device__ int   g_cls[NROWS];
__device__ float g_loss;
__device__ int   g_cnt;
__device__ int   g_done;

// ---------------- PTX helpers (all base-sm_103 legal) ----------------
__device__ __forceinline__ uint32_t smem_u32(const void* p) {
    uint32_t a;
    asm("{ .reg .u64 t; cvta.to.shared.u64 t, %1; cvt.u32.u64 %0, t; }" : "=r"(a) : "l"(p));
    return a;
}

#define CP_ASYNC16(dst_u32, src_ptr) \
    asm volatile("{ .reg .u64 g; cvta.to.global.u64 g, %1; cp.async.cg.shared.global [%0], [g], 16; }" \
                 :: "r"(dst_u32), "l"(src_ptr) : "memory")
#define CP_COMMIT() asm volatile("cp.async.commit_group;" ::: "memory")
#define CP_WAIT(n)  asm volatile("cp.async.wait_group %0;" :: "n"(n) : "memory")

#define LDSM_X4(r, addr) \
    asm volatile("ldmatrix.sync.aligned.m8n8.x4.shared.b16 {%0,%1,%2,%3}, [%4];" \
                 : "=r"((r)[0]), "=r"((r)[1]), "=r"((r)[2]), "=r"((r)[3]) : "r"(addr))

#define MMA_BF16(d, a, b0, b1) \
    asm volatile("mma.sync.aligned.m16n8k16.row.col.f32.bf16.bf16.f32 " \
                 "{%0,%1,%2,%3}, {%4,%5,%6,%7}, {%8,%9}, {%0,%1,%2,%3};" \
                 : "+f"((d)[0]), "+f"((d)[1]), "+f"((d)[2]), "+f"((d)[3]) \
                 : "r"((a)[0]), "r"((a)[1]), "r"((a)[2]), "r"((a)[3]), "r"(b0), "r"(b1))

// ---------------- Pass 1: convert + row norms + class ids + zero accumulators ----------------
__global__ __launch_bounds__(256) void pass1_kernel(const float* __restrict__ X,
                                                    const int* __restrict__ TW) {
    int tid = threadIdx.x;
    // Detect target dtype: if buffer is int64 (LE, values < 64), every odd 32-bit
    // word of the first 512 words is 0; if int32, those words are class ids.
    int pred = (TW[2 * tid + 1] != 0);
    int is32 = __syncthreads_or(pred);

    int wid = tid >> 5, lid = tid & 31;
    int row = blockIdx.x * 8 + wid;
    const float4* src = (const float4*)(X + (size_t)row * DDIM);
    float s = 0.f;
#pragma unroll
    for (int t = 0; t < 4; t++) {
        float4 v = src[lid + 32 * t];
        s = fmaf(v.x, v.x, s); s = fmaf(v.y, v.y, s);
        s = fmaf(v.z, v.z, s); s = fmaf(v.w, v.w, s);
        __nv_bfloat162 p0 = __floats2bfloat162_rn(v.x, v.y);
        __nv_bfloat162 p1 = __floats2bfloat162_rn(v.z, v.w);
        uint2 u;
        u.x = *(const uint32_t*)&p0;
        u.y = *(const uint32_t*)&p1;
        *(uint2*)(g_Xb + (size_t)row * DDIM + (lid + 32 * t) * 4) = u;
    }
#pragma unroll
    for (int o = 16; o; o >>= 1) s += __shfl_xor_sync(0xffffffffu, s, o);
    if (lid == 0) {
        g_sq[row] = s;
        g_negsum[row] = 0.f;
        g_cls[row] = is32 ? TW[row] : TW[2 * row];
    }
    if (blockIdx.x == 0 && tid == 0) { g_loss = 0.f; g_cnt = 0; }
}

// ---------------- Pass 2: HMMA GEMM, triangle-only grid + fused row+col neg_sum epilogue ----
#define SM_SQI  0
#define SM_SQJ  512
#define SM_CI   1024
#define SM_CJ   1536
#define SM_NEGR 2048
#define SM_NEGC 2560
#define SM_A0   3072
#define SM_A1   21504
#define SM_B0   39936
#define SM_B1   58368
#define SM2_TOTAL 76800

__global__ __launch_bounds__(256, 2) void pass2_kernel() {
    // linear tile id -> (I, J) with J >= I over 32x32 block grid
    int rem = blockIdx.x, I = 0, rowlen = 32;
    while (rem >= rowlen) { rem -= rowlen; rowlen--; I++; }
    int J = I + rem;

    extern __shared__ char smem[];
    uint32_t sb = smem_u32(smem);
    int tid = threadIdx.x;
    int lane = tid & 31, wid = tid >> 5;
    int warp_m = wid >> 2, warp_n = wid & 3;           // 2 x 4 warp grid
    int m0 = warp_m * 64, n0 = warp_n * 32;            // 64x32 per warp
    int rowA0 = I * BM;
    int rowB0 = J * BM;

    float* sSqi = (float*)(smem + SM_SQI);
    float* sSqj = (float*)(smem + SM_SQJ);
    int*   sCi  = (int*)(smem + SM_CI);
    int*   sCj  = (int*)(smem + SM_CJ);
    float* sNegR = (float*)(smem + SM_NEGR);
    float* sNegC = (float*)(smem + SM_NEGC);

    if (tid < 128) {
        sSqi[tid] = g_sq[rowA0 + tid];
        sCi[tid]  = g_cls[rowA0 + tid];
        sNegR[tid] = 0.f;
    } else {
        int r = tid - 128;
        sSqj[r] = g_sq[rowB0 + r];
        sCj[r]  = g_cls[rowB0 + r];
        sNegC[r] = 0.f;
    }

    float acc[4][4][4];
#pragma unroll
    for (int i = 0; i < 4; i++)
#pragma unroll
        for (int j = 0; j < 4; j++)
#pragma unroll
            for (int e = 0; e < 4; e++) acc[i][j][e] = 0.f;

    auto issue = [&](int c, int b) {
        const __nv_bfloat16* gA = g_Xb + (size_t)rowA0 * DDIM + c * BK;
        const __nv_bfloat16* gB = g_Xb + (size_t)rowB0 * DDIM + c * BK;
        uint32_t dA = sb + (b ? SM_A1 : SM_A0);
        uint32_t dB = sb + (b ? SM_B1 : SM_B0);
#pragma unroll
        for (int t = 0; t < 4; t++) {
            int idx = tid + t * 256;           // 0..1023
            int r = idx >> 3, kk = idx & 7;    // 128 rows x 8 x 16B
            uint32_t doff = r * (SSTR * 2) + kk * 16;
            CP_ASYNC16(dA + doff, (const char*)gA + (size_t)r * (DDIM * 2) + kk * 16);
            CP_ASYNC16(dB + doff, (const char*)gB + (size_t)r * (DDIM * 2) + kk * 16);
        }
    };

    issue(0, 0);
    CP_COMMIT();

    int g  = lane >> 3, l8 = lane & 7;
    int arow = (g & 1) * 8 + l8, akoff = (g >> 1) * 8;
    int brow = (g >> 1) * 8 + l8, bkoff = (g & 1) * 8;

    for (int c = 0; c < NCHUNK; c++) {
        int b = c & 1;
        if (c + 1 < NCHUNK) { issue(c + 1, b ^ 1); CP_COMMIT(); CP_WAIT(1); }
        else                { CP_WAIT(0); }
        __syncthreads();

        uint32_t sA = sb + (b ? SM_A1 : SM_A0);
        uint32_t sB = sb + (b ? SM_B1 : SM_B0);
#pragma unroll
        for (int ks = 0; ks < 4; ks++) {
            int k0 = ks * 16;
            uint32_t afr[4][4];
#pragma unroll
            for (int mf = 0; mf < 4; mf++) {
                uint32_t ad = sA + 2u * ((m0 + mf * 16 + arow) * SSTR + k0 + akoff);
                LDSM_X4(afr[mf], ad);
            }
            uint32_t bfr[2][4];
#pragma unroll
            for (int p = 0; p < 2; p++) {
                uint32_t bd = sB + 2u * ((n0 + p * 16 + brow) * SSTR + k0 + bkoff);
                LDSM_X4(bfr[p], bd);
            }
#pragma unroll
            for (int mf = 0; mf < 4; mf++)
#pragma unroll
                for (int nf = 0; nf < 4; nf++) {
                    uint32_t b0 = bfr[nf >> 1][(nf & 1) * 2];
                    uint32_t b1 = bfr[nf >> 1][(nf & 1) * 2 + 1];
                    MMA_BF16(acc[mf][nf], afr[mf], b0, b1);
                }
        }
        __syncthreads();
    }

    // --- Epilogue ---
    int qr = lane >> 2, qc = lane & 3;
    float colacc[8];
#pragma unroll
    for (int t = 0; t < 8; t++) colacc[t] = 0.f;

#pragma unroll
    for (int mf = 0; mf < 4; mf++) {
        int il0 = m0 + mf * 16 + qr;
        int il1 = il0 + 8;
        float sq0 = sSqi[il0], sq1 = sSqi[il1];
        int   cc0 = sCi[il0],  cc1 = sCi[il1];
        float s0 = 0.f, s1 = 0.f;
#pragma unroll
        for (int nf = 0; nf < 4; nf++) {
            int jl = n0 + nf * 8 + 2 * qc;
#pragma unroll
            for (int e = 0; e < 2; e++) {
                int j = jl + e;
                float sqj = sSqj[j];
                int   cj  = sCj[j];
                float d2a = fmaxf(fmaf(-2.f, acc[mf][nf][e], sq0 + sqj), 0.f);
                float da; asm("sqrt.approx.f32 %0, %1;" : "=f"(da) : "f"(d2a));
                float ea; asm("ex2.approx.f32 %0, %1;" : "=f"(ea) : "f"((1.0f - da) * 1.4426950408889634f));
                float d2b = fmaxf(fmaf(-2.f, acc[mf][nf][2 + e], sq1 + sqj), 0.f);
                float db; asm("sqrt.approx.f32 %0, %1;" : "=f"(db) : "f"(d2b));
                float eb; asm("ex2.approx.f32 %0, %1;" : "=f"(eb) : "f"((1.0f - db) * 1.4426950408889634f));
                float fa = (cc0 != cj) ? ea : 0.f;
                float fb = (cc1 != cj) ? eb : 0.f;
                s0 += fa;
                s1 += fb;
                colacc[nf * 2 + e] += fa + fb;
            }
        }
        s0 += __shfl_xor_sync(0xffffffffu, s0, 1);
        s0 += __shfl_xor_sync(0xffffffffu, s0, 2);
        s1 += __shfl_xor_sync(0xffffffffu, s1, 1);
        s1 += __shfl_xor_sync(0xffffffffu, s1, 2);
        if (qc == 0) {
            atomicAdd(&sNegR[il0], s0);
            atomicAdd(&sNegR[il1], s1);
        }
    }

    if (J > I) {
#pragma unroll
        for (int t = 0; t < 8; t++) {
            float v = colacc[t];
            v += __shfl_xor_sync(0xffffffffu, v, 4);
            v += __shfl_xor_sync(0xffffffffu, v, 8);
            v += __shfl_xor_sync(0xffffffffu, v, 16);
            if (qr == 0) {
                int j = n0 + (t >> 1) * 8 + 2 * qc + (t & 1);
                atomicAdd(&sNegC[j], v);
            }
        }
    }

    __syncthreads();
    if (tid < 128) {
        atomicAdd(&g_negsum[rowA0 + tid], sNegR[tid]);
    } else if (J > I) {
        int r = tid - 128;
        atomicAdd(&g_negsum[rowB0 + r], sNegC[r]);
    }
}

// ---------------- Pass 3: positive pairs (dual-pair ILP) + fused finalize ----------------
#define P3Y 4                      // grid = (64, P3Y), 256 threads -> 32 warp slots/class

__global__ __launch_bounds__(256) void pass3_kernel(const float* __restrict__ X, float* out) {
    __shared__ int members[256];
    __shared__ int wcnt[8];
    int tid = threadIdx.x, wid = tid >> 5, lane = tid & 31;
    int cls = blockIdx.x;

    // Deterministic ballot-based compaction (identical ordering in all CTAs).
    int base = wid * 512;
    int cnt = 0;
#pragma unroll 4
    for (int r = 0; r < 16; r++) {
        int row = base + r * 32 + lane;
        unsigned mask = __ballot_sync(0xffffffffu, g_cls[row] == cls);
        cnt += __popc(mask);
    }
    if (lane == 0) wcnt[wid] = cnt;
    __syncthreads();
    int start = 0, ntot = 0;
#pragma unroll
    for (int w = 0; w < 8; w++) {
        int c = wcnt[w];
        if (w < wid) start += c;
        ntot += c;
    }
    int run = start;
#pragma unroll 4
    for (int r = 0; r < 16; r++) {
        int row = base + r * 32 + lane;
        bool mm = (g_cls[row] == cls);
        unsigned mask = __ballot_sync(0xffffffffu, mm);
        int pos = run + __popc(mask & ((1u << lane) - 1u));
        if (mm && pos < 256) members[pos] = row;
        run += __popc(mask);
    }
    __syncthreads();
    int n = min(ntot, 256);
    if (blockIdx.y == 0 && tid == 0 && n > 1) atomicAdd(&g_cnt, n * (n - 1));

    float loss = 0.f;
    if (n >= 2) {
        // Mirrored-balanced a-assignment: slot s handles a in {64*blk + s, 64*blk + 63 - s}.
        int s = blockIdx.y * 8 + wid;    // 0..31
        const float4* X4 = (const float4*)X;

#pragma unroll 1
        for (int k = 0; k < 8; k++) {
            int blk = k >> 1;
            int a = 64 * blk + ((k & 1) ? (63 - s) : s);
            if (a > n - 2) continue;
            int ga = members[a];
            float4 va[4];
#pragma unroll
            for (int q = 0; q < 4; q++) va[q] = __ldg(&X4[(size_t)ga * 128 + lane + 32 * q]);
            float nsa = g_negsum[ga];

            int b = a + 1;
#pragma unroll 1
            for (; b + 1 < n; b += 2) {
                int gb0 = members[b], gb1 = members[b + 1];
                float acc0 = 0.f, acc1 = 0.f;
#pragma unroll
                for (int q = 0; q < 4; q++) {
                    float4 v0 = __ldg(&X4[(size_t)gb0 * 128 + lane + 32 * q]);
                    float4 v1 = __ldg(&X4[(size_t)gb1 * 128 + lane + 32 * q]);
                    float d0x = va[q].x - v0.x, d0y = va[q].y - v0.y;
                    float d0z = va[q].z - v0.z, d0w = va[q].w - v0.w;
                    float d1x = va[q].x - v1.x, d1y = va[q].y - v1.y;
                    float d1z = va[q].z - v1.z, d1w = va[q].w - v1.w;
                    acc0 = fmaf(d0x, d0x, acc0); acc1 = fmaf(d1x, d1x, acc1);
                    acc0 = fmaf(d0y, d0y, acc0); acc1 = fmaf(d1y, d1y, acc1);
                    acc0 = fmaf(d0z, d0z, acc0); acc1 = fmaf(d1z, d1z, acc1);
                    acc0 = fmaf(d0w, d0w, acc0); acc1 = fmaf(d1w, d1w, acc1);
                }
#pragma unroll
                for (int o = 16; o; o >>= 1) {
                    acc0 += __shfl_xor_sync(0xffffffffu, acc0, o);
                    acc1 += __shfl_xor_sync(0xffffffffu, acc1, o);
                }
                if (lane == 0) {
                    float ns0 = nsa + g_negsum[gb0];
                    float ns1 = nsa + g_negsum[gb1];
                    float J0 = __logf(ns0) + sqrtf(acc0);
                    float J1 = __logf(ns1) + sqrtf(acc1);
                    float h0 = fmaxf(J0, 0.f);
                    float h1 = fmaxf(J1, 0.f);
                    loss = fmaf(h0, h0, loss);
                    loss = fmaf(h1, h1, loss);
                }
            }
            if (b < n) {   // tail pair
                int gb = members[b];
                float acc = 0.f;
#pragma unroll
                for (int q = 0; q < 4; q++) {
                    float4 vb = __ldg(&X4[(size_t)gb * 128 + lane + 32 * q]);
                    float dx = va[q].x - vb.x, dy = va[q].y - vb.y;
                    float dz = va[q].z - vb.z, dw = va[q].w - vb.w;
                    acc = fmaf(dx, dx, acc); acc = fmaf(dy, dy, acc);
                    acc = fmaf(dz, dz, acc); acc = fmaf(dw, dw, acc);
                }
#pragma unroll
                for (int o = 16; o; o >>= 1) acc += __shfl_xor_sync(0xffffffffu, acc, o);
                if (lane == 0) {
                    float ns = nsa + g_negsum[gb];
                    float Jv = __logf(ns) + sqrtf(acc);
                    float h = fmaxf(Jv, 0.f);
                    loss = fmaf(h, h, loss);
                }
            }
        }
    }
    if (lane == 0 && loss != 0.f) atomicAdd(&g_loss, loss);
    __syncthreads();

    // Fused finalize: last-done CTA writes the output (replaces pass4 launch).
    if (tid == 0) {
        __threadfence();   // make this CTA's g_loss atomic globally visible before done-count
        int done = atomicAdd(&g_done, 1);
        if (done == NCLS * P3Y - 1) {
            float L = atomicAdd(&g_loss, 0.f);   // atomic read: coherent at L2
            int   C = atomicAdd(&g_cnt, 0);
            out[0] = (C > 0) ? (L / (float)C) : 0.f;
            g_done = 0;                           // reset for next graph replay
        }
    }
}

// ---------------- host ----------------
extern "C" void kernel_launch(void* const* d_in, const int* in_sizes, int n_in,
                              void* d_out, int out_size) {
    const float* X  = (const float*)d_in[0];
    const int*   TW = (const int*)d_in[1];   // targets: int32 or int64 (auto-detected)
    float* out = (float*)d_out;

    cudaFuncSetAttribute(pass2_kernel, cudaFuncAttributeMaxDynamicSharedMemorySize, SM2_TOTAL);

    pass1_kernel<<<NROWS / 8, 256>>>(X, TW);
    pass2_kernel<<<NTILES, 256, SM2_TOTAL>>>();
    pass3_kernel<<<dim3(NCLS, P3Y), 256>>>(X, out);
}